// round 1
// baseline (speedup 1.0000x reference)
#include <cuda_runtime.h>
#include <math.h>

// ---------------- problem constants ----------------
#define NBS   2
#define NR    512
#define NROI  (NBS*NR)          // 1024
#define CH    256
#define OUTS  7
#define NPIX  (OUTS*OUTS)       // 49
#define FDIM  (CH*NPIX)         // 12544
#define DDIM  1024
#define NCLS  81
#define NREG  320

// ---------------- device scratch (no cudaMalloc allowed) ----------------
__device__ float g_X[(size_t)NROI * FDIM];   // pooled roi features [N, 12544]
__device__ float g_Y[(size_t)NROI * DDIM];   // fc1 out
__device__ float g_Z[(size_t)NROI * DDIM];   // fc2 out
__device__ int   g_lvl[NROI];                // fpn level index 0..3, or out-of-range
__device__ float g_meta[NROI * 4];           // x1s, y1s, bin_w, bin_h (scaled coords)

// ---------------- roi prep: level routing + scaled coords ----------------
__global__ void roi_prep_kernel(const float* __restrict__ rois) {
    int i = blockIdx.x * blockDim.x + threadIdx.x;
    if (i >= NROI) return;
    float x1 = rois[i * 4 + 0];
    float y1 = rois[i * 4 + 1];
    float x2 = rois[i * 4 + 2];
    float y2 = rois[i * 4 + 3];
    float w = x2 - x1, h = y2 - y1;
    // lv = floor(4 + log2(sqrt(w*h)/224 + 1e-6)), unclamped (matches reference)
    float lv = floorf(4.0f + log2f(sqrtf(w * h) / 224.0f + 1e-6f));
    int li = (int)lv - 2;   // 0..3 valid
    g_lvl[i] = li;
    int lic = li < 0 ? 0 : (li > 3 ? 3 : li);
    float scale = 1.0f / (float)(4 << lic);   // exact powers of 2
    float x1s = x1 * scale, y1s = y1 * scale;
    float rw = fmaxf(x2 * scale - x1s, 1.0f); // max AFTER scaling, as in reference
    float rh = fmaxf(y2 * scale - y1s, 1.0f);
    g_meta[i * 4 + 0] = x1s;
    g_meta[i * 4 + 1] = y1s;
    g_meta[i * 4 + 2] = rw / (float)OUTS;
    g_meta[i * 4 + 3] = rh / (float)OUTS;
}

// ---------------- roi align: one thread per output element ----------------
__global__ void roi_align_kernel(const float* __restrict__ f2,
                                 const float* __restrict__ f3,
                                 const float* __restrict__ f4,
                                 const float* __restrict__ f5) {
    int idx = blockIdx.x * blockDim.x + threadIdx.x;
    if (idx >= NROI * CH * NPIX) return;
    int n   = idx / (CH * NPIX);
    int rem = idx - n * (CH * NPIX);
    int c   = rem / NPIX;
    int p   = rem - c * NPIX;

    int li = g_lvl[n];
    if (li < 0 || li > 3) { g_X[idx] = 0.0f; return; }

    int ph = p / OUTS, pw = p - ph * OUTS;

    const float* f; int H;
    if      (li == 0) { f = f2; H = 200; }
    else if (li == 1) { f = f3; H = 100; }
    else if (li == 2) { f = f4; H = 50;  }
    else              { f = f5; H = 25;  }
    int W = H;
    int b = (n >= NR) ? 1 : 0;
    const float* base = f + ((size_t)b * CH + c) * (size_t)(H * W);

    float x1 = g_meta[n * 4 + 0];
    float y1 = g_meta[n * 4 + 1];
    float bw = g_meta[n * 4 + 2];
    float bh = g_meta[n * 4 + 3];

    float acc = 0.0f;
    #pragma unroll
    for (int iy = 0; iy < 2; iy++) {
        // sample offsets g = {0.25, 0.75}
        float y = y1 + ((float)ph + 0.25f + 0.5f * (float)iy) * bh;
        bool vy = (y > -1.0f) && (y < (float)H);
        float yc = fminf(fmaxf(y, 0.0f), (float)(H - 1));
        float y0f = floorf(yc);
        int y0 = (int)y0f;
        int yb = min(y0 + 1, H - 1);
        float ly = yc - y0f;
        const float* row0 = base + (size_t)y0 * W;
        const float* row1 = base + (size_t)yb * W;
        #pragma unroll
        for (int ix = 0; ix < 2; ix++) {
            float x = x1 + ((float)pw + 0.25f + 0.5f * (float)ix) * bw;
            bool vx = (x > -1.0f) && (x < (float)W);
            if (vy && vx) {
                float xc = fminf(fmaxf(x, 0.0f), (float)(W - 1));
                float x0f = floorf(xc);
                int x0 = (int)x0f;
                int xb = min(x0 + 1, W - 1);
                float lx = xc - x0f;
                float v = (1.0f - ly) * ((1.0f - lx) * row0[x0] + lx * row0[xb])
                        +          ly * ((1.0f - lx) * row1[x0] + lx * row1[xb]);
                acc += v;
            }
        }
    }
    g_X[idx] = acc * 0.25f;   // mean over 2x2 samples (invalid contribute 0)
}

// ---------------- SGEMM NT: C[M,N] = A[M,K] * B[N,K]^T + bias (optional relu) ----
// BM=128, BN=64, BK=16, 256 threads, 8x4 microtile. Requires M%128==0, N%64==0, K%16==0.
__global__ void __launch_bounds__(256)
sgemm_nt_kernel(const float* __restrict__ A, const float* __restrict__ B,
                const float* __restrict__ bias, float* __restrict__ C,
                int M, int N, int K, int relu) {
    __shared__ float As[16][128];
    __shared__ float Bs[16][64];

    const int tid = threadIdx.x;
    const int tx = tid & 15;        // 0..15 -> N microtile
    const int ty = tid >> 4;        // 0..15 -> M microtile
    const int lr = tid >> 2;        // 0..63 load row
    const int lk = (tid & 3) << 2;  // 0,4,8,12 load k offset

    const float* Ab = A + (size_t)(blockIdx.y * 128) * K;
    const float* Bb = B + (size_t)(blockIdx.x * 64) * K;

    float acc[8][4];
    #pragma unroll
    for (int i = 0; i < 8; i++)
        #pragma unroll
        for (int j = 0; j < 4; j++) acc[i][j] = 0.0f;

    for (int kt = 0; kt < K; kt += 16) {
        float4 a0 = *(const float4*)(Ab + (size_t)lr * K + kt + lk);
        float4 a1 = *(const float4*)(Ab + (size_t)(lr + 64) * K + kt + lk);
        float4 b0 = *(const float4*)(Bb + (size_t)lr * K + kt + lk);
        As[lk + 0][lr] = a0.x; As[lk + 1][lr] = a0.y; As[lk + 2][lr] = a0.z; As[lk + 3][lr] = a0.w;
        As[lk + 0][lr + 64] = a1.x; As[lk + 1][lr + 64] = a1.y; As[lk + 2][lr + 64] = a1.z; As[lk + 3][lr + 64] = a1.w;
        Bs[lk + 0][lr] = b0.x; Bs[lk + 1][lr] = b0.y; Bs[lk + 2][lr] = b0.z; Bs[lk + 3][lr] = b0.w;
        __syncthreads();
        #pragma unroll
        for (int k = 0; k < 16; k++) {
            float4 av0 = *(const float4*)&As[k][ty * 8];
            float4 av1 = *(const float4*)&As[k][ty * 8 + 4];
            float4 bv  = *(const float4*)&Bs[k][tx * 4];
            float a[8] = {av0.x, av0.y, av0.z, av0.w, av1.x, av1.y, av1.z, av1.w};
            float bb[4] = {bv.x, bv.y, bv.z, bv.w};
            #pragma unroll
            for (int i = 0; i < 8; i++)
                #pragma unroll
                for (int j = 0; j < 4; j++)
                    acc[i][j] = fmaf(a[i], bb[j], acc[i][j]);
        }
        __syncthreads();
    }

    #pragma unroll
    for (int i = 0; i < 8; i++) {
        int row = blockIdx.y * 128 + ty * 8 + i;
        #pragma unroll
        for (int j = 0; j < 4; j++) {
            int col = blockIdx.x * 64 + tx * 4 + j;
            float v = acc[i][j] + bias[col];
            if (relu) v = fmaxf(v, 0.0f);
            C[(size_t)row * N + col] = v;
        }
    }
}

// ---------------- heads: cls (81) + reg (320), 8 rows per block ----------------
__global__ void __launch_bounds__(256)
heads_kernel(const float* __restrict__ Z,
             const float* __restrict__ Wc, const float* __restrict__ bc,
             const float* __restrict__ Wr, const float* __restrict__ br,
             float* __restrict__ out) {
    __shared__ float zs[8][DDIM];
    int m0 = blockIdx.x * 8;
    for (int i = threadIdx.x; i < 8 * DDIM; i += blockDim.x)
        zs[i >> 10][i & 1023] = Z[(size_t)(m0 + (i >> 10)) * DDIM + (i & 1023)];
    __syncthreads();

    for (int n = threadIdx.x; n < NCLS + NREG; n += blockDim.x) {
        const float* w;
        float bb;
        if (n < NCLS) { w = Wc + (size_t)n * DDIM; bb = bc[n]; }
        else          { w = Wr + (size_t)(n - NCLS) * DDIM; bb = br[n - NCLS]; }
        float acc[8];
        #pragma unroll
        for (int r = 0; r < 8; r++) acc[r] = bb;
        for (int k = 0; k < DDIM; k += 4) {
            float4 wv = *(const float4*)(w + k);
            #pragma unroll
            for (int r = 0; r < 8; r++) {
                acc[r] = fmaf(zs[r][k + 0], wv.x, acc[r]);
                acc[r] = fmaf(zs[r][k + 1], wv.y, acc[r]);
                acc[r] = fmaf(zs[r][k + 2], wv.z, acc[r]);
                acc[r] = fmaf(zs[r][k + 3], wv.w, acc[r]);
            }
        }
        #pragma unroll
        for (int r = 0; r < 8; r++) {
            int m = m0 + r;
            if (n < NCLS) out[(size_t)m * NCLS + n] = acc[r];
            else out[(size_t)NROI * NCLS + (size_t)m * NREG + (n - NCLS)] = acc[r];
        }
    }
}

// ---------------- launch ----------------
extern "C" void kernel_launch(void* const* d_in, const int* in_sizes, int n_in,
                              void* d_out, int out_size) {
    const float* f2   = (const float*)d_in[0];
    const float* f3   = (const float*)d_in[1];
    const float* f4   = (const float*)d_in[2];
    const float* f5   = (const float*)d_in[3];
    const float* rois = (const float*)d_in[4];
    const float* W1   = (const float*)d_in[5];
    const float* b1   = (const float*)d_in[6];
    const float* W2   = (const float*)d_in[7];
    const float* b2   = (const float*)d_in[8];
    const float* Wc   = (const float*)d_in[9];
    const float* bc   = (const float*)d_in[10];
    const float* Wr   = (const float*)d_in[11];
    const float* br   = (const float*)d_in[12];
    float* out = (float*)d_out;

    float *X, *Y, *Z;
    cudaGetSymbolAddress((void**)&X, g_X);
    cudaGetSymbolAddress((void**)&Y, g_Y);
    cudaGetSymbolAddress((void**)&Z, g_Z);

    roi_prep_kernel<<<(NROI + 255) / 256, 256>>>(rois);

    int total = NROI * CH * NPIX;
    roi_align_kernel<<<(total + 255) / 256, 256>>>(f2, f3, f4, f5);

    // fc1: [1024, 12544] x [1024, 12544]^T -> [1024, 1024], relu
    sgemm_nt_kernel<<<dim3(DDIM / 64, NROI / 128), 256>>>(X, W1, b1, Y,
                                                          NROI, DDIM, FDIM, 1);
    // fc2: [1024, 1024] x [1024, 1024]^T -> [1024, 1024], relu
    sgemm_nt_kernel<<<dim3(DDIM / 64, NROI / 128), 256>>>(Y, W2, b2, Z,
                                                          NROI, DDIM, DDIM, 1);
    // heads -> d_out (cls first, then reg)
    heads_kernel<<<NROI / 8, 256>>>(Z, Wc, bc, Wr, br, out);
}

// round 3
// speedup vs baseline: 2.4045x; 2.4045x over previous
#include <cuda_runtime.h>
#include <cstdint>
#include <math.h>

// ---------------- problem constants ----------------
#define NBS   2
#define NR    512
#define NROI  (NBS*NR)          // 1024
#define CH    256
#define OUTS  7
#define NPIX  (OUTS*OUTS)       // 49
#define FDIM  (CH*NPIX)         // 12544
#define DDIM  1024
#define NCLS  81
#define NREG  320

// ---------------- device scratch ----------------
__device__ float g_X[(size_t)NROI * FDIM];     // pooled roi features (tf32-rounded)
__device__ float g_Y[(size_t)NROI * DDIM];     // fc1 out (tf32-rounded)
__device__ float g_Z[(size_t)NROI * DDIM];     // fc2 out (fp32)
__device__ float g_W1r[(size_t)DDIM * FDIM];   // tf32-rounded W1
__device__ float g_W2r[(size_t)DDIM * DDIM];   // tf32-rounded W2
__device__ int   g_lvl[NROI];
__device__ float g_meta[NROI * 4];

// ---------------- helpers ----------------
__device__ __forceinline__ float tf32_rna(float x) {
    uint32_t r; asm("cvt.rna.tf32.f32 %0, %1;" : "=r"(r) : "f"(x));
    return __uint_as_float(r);
}
__device__ __forceinline__ uint32_t smem_u32(const void* p) {
    uint32_t a;
    asm("{ .reg .u64 t; cvta.to.shared.u64 t, %1; cvt.u32.u64 %0, t; }" : "=r"(a) : "l"(p));
    return a;
}
#define CP16(dst, src) \
    asm volatile("cp.async.cg.shared.global [%0], [%1], 16;" :: "r"(dst), "l"(src) : "memory")
#define CPCOMMIT() asm volatile("cp.async.commit_group;" ::: "memory")
#define CPWAIT2()  asm volatile("cp.async.wait_group 2;" ::: "memory")

__device__ __forceinline__ void mma_tf32(float c[4], const uint32_t a[4], const uint32_t b[2]) {
    asm volatile(
        "mma.sync.aligned.m16n8k8.row.col.f32.tf32.tf32.f32 "
        "{%0,%1,%2,%3}, {%4,%5,%6,%7}, {%8,%9}, {%0,%1,%2,%3};"
        : "+f"(c[0]), "+f"(c[1]), "+f"(c[2]), "+f"(c[3])
        : "r"(a[0]), "r"(a[1]), "r"(a[2]), "r"(a[3]), "r"(b[0]), "r"(b[1]));
}

// ---------------- roi prep ----------------
__global__ void roi_prep_kernel(const float* __restrict__ rois) {
    int i = blockIdx.x * blockDim.x + threadIdx.x;
    if (i >= NROI) return;
    float x1 = rois[i * 4 + 0], y1 = rois[i * 4 + 1];
    float x2 = rois[i * 4 + 2], y2 = rois[i * 4 + 3];
    float w = x2 - x1, h = y2 - y1;
    float lv = floorf(4.0f + log2f(sqrtf(w * h) / 224.0f + 1e-6f));
    int li = (int)lv - 2;
    g_lvl[i] = li;
    int lic = li < 0 ? 0 : (li > 3 ? 3 : li);
    float scale = 1.0f / (float)(4 << lic);
    float x1s = x1 * scale, y1s = y1 * scale;
    float rw = fmaxf(x2 * scale - x1s, 1.0f);
    float rh = fmaxf(y2 * scale - y1s, 1.0f);
    g_meta[i * 4 + 0] = x1s;
    g_meta[i * 4 + 1] = y1s;
    g_meta[i * 4 + 2] = rw / (float)OUTS;
    g_meta[i * 4 + 3] = rh / (float)OUTS;
}

// ---------------- roi align (writes tf32-rounded X) ----------------
__global__ void roi_align_kernel(const float* __restrict__ f2,
                                 const float* __restrict__ f3,
                                 const float* __restrict__ f4,
                                 const float* __restrict__ f5) {
    int idx = blockIdx.x * blockDim.x + threadIdx.x;
    if (idx >= NROI * CH * NPIX) return;
    int n   = idx / (CH * NPIX);
    int rem = idx - n * (CH * NPIX);
    int c   = rem / NPIX;
    int p   = rem - c * NPIX;

    int li = g_lvl[n];
    if (li < 0 || li > 3) { g_X[idx] = 0.0f; return; }

    int ph = p / OUTS, pw = p - ph * OUTS;
    const float* f; int H;
    if      (li == 0) { f = f2; H = 200; }
    else if (li == 1) { f = f3; H = 100; }
    else if (li == 2) { f = f4; H = 50;  }
    else              { f = f5; H = 25;  }
    int W = H;
    int b = (n >= NR) ? 1 : 0;
    const float* base = f + ((size_t)b * CH + c) * (size_t)(H * W);

    float x1 = g_meta[n * 4 + 0], y1 = g_meta[n * 4 + 1];
    float bw = g_meta[n * 4 + 2], bh = g_meta[n * 4 + 3];

    float acc = 0.0f;
    #pragma unroll
    for (int iy = 0; iy < 2; iy++) {
        float y = y1 + ((float)ph + 0.25f + 0.5f * (float)iy) * bh;
        bool vy = (y > -1.0f) && (y < (float)H);
        float yc = fminf(fmaxf(y, 0.0f), (float)(H - 1));
        float y0f = floorf(yc);
        int y0 = (int)y0f;
        int yb = min(y0 + 1, H - 1);
        float ly = yc - y0f;
        const float* row0 = base + (size_t)y0 * W;
        const float* row1 = base + (size_t)yb * W;
        #pragma unroll
        for (int ix = 0; ix < 2; ix++) {
            float x = x1 + ((float)pw + 0.25f + 0.5f * (float)ix) * bw;
            bool vx = (x > -1.0f) && (x < (float)W);
            if (vy && vx) {
                float xc = fminf(fmaxf(x, 0.0f), (float)(W - 1));
                float x0f = floorf(xc);
                int x0 = (int)x0f;
                int xb = min(x0 + 1, W - 1);
                float lx = xc - x0f;
                float v = (1.0f - ly) * ((1.0f - lx) * row0[x0] + lx * row0[xb])
                        +          ly * ((1.0f - lx) * row1[x0] + lx * row1[xb]);
                acc += v;
            }
        }
    }
    g_X[idx] = tf32_rna(acc * 0.25f);
}

// ---------------- elementwise tf32 round (weights) ----------------
__global__ void round_tf32_kernel(const float4* __restrict__ in,
                                  float4* __restrict__ out, int n4) {
    int i = blockIdx.x * blockDim.x + threadIdx.x;
    if (i >= n4) return;
    float4 v = in[i];
    v.x = tf32_rna(v.x); v.y = tf32_rna(v.y);
    v.z = tf32_rna(v.z); v.w = tf32_rna(v.w);
    out[i] = v;
}

// ---------------- mma.sync tf32 GEMM (HMMA path) ----------------
// C[M,DDIM] = A[M,K] * B[DDIM,K]^T + bias; tile 128x64, BK=16, 4-stage cp.async.
// 256 threads, 8 warps (4 M x 2 N), warp tile 32x32, m16n8k8 atoms.
#define PADK   20                 // smem row stride (floats); 20 mod 32 cycles banks
#define ASZ    (128 * PADK)       // floats per A stage
#define BSZ    (64  * PADK)       // floats per B stage
#define GSMEM  ((4 * (ASZ + BSZ)) * 4)   // bytes = 61440

__global__ void __launch_bounds__(256, 1)
gemm_mma_tf32(const float* __restrict__ A, const float* __restrict__ B,
              const float* __restrict__ bias, float* __restrict__ C,
              int K, int relu, int rnd) {
    extern __shared__ float sm[];
    float* smA = sm;
    float* smB = sm + 4 * ASZ;
    uint32_t sA = smem_u32(smA);
    uint32_t sB = smem_u32(smB);

    const int tid = threadIdx.x;
    const int wid = tid >> 5, lane = tid & 31;
    const int grp = lane >> 2, tig = lane & 3;
    const int wm = (wid & 3) * 32;       // warp M offset in tile
    const int wn = (wid >> 2) * 32;      // warp N offset in tile

    const int rowA0 = blockIdx.y * 128;
    const int colB0 = blockIdx.x * 64;
    const int nk = K >> 4;

    // global load mapping
    const int arow = tid >> 1, ac = (tid & 1) * 8;        // A: 2 float4 per thread
    const int brow = tid >> 2, bc = (tid & 3) * 4;        // B: 1 float4 per thread
    const float* gA = A + (size_t)(rowA0 + arow) * K + ac;
    const float* gB = B + (size_t)(colB0 + brow) * K + bc;
    const uint32_t dA0 = sA + (uint32_t)(arow * PADK + ac) * 4;
    const uint32_t dA1 = dA0 + 16;
    const uint32_t dB0 = sB + (uint32_t)(brow * PADK + bc) * 4;

    float c[2][4][4];
    #pragma unroll
    for (int i = 0; i < 2; i++)
        #pragma unroll
        for (int j = 0; j < 4; j++)
            #pragma unroll
            for (int q = 0; q < 4; q++) c[i][j][q] = 0.0f;

    // prologue: stages 0..2
    #pragma unroll
    for (int s = 0; s < 3; s++) {
        if (s < nk) {
            CP16(dA0 + (uint32_t)(s * ASZ * 4), gA + (size_t)s * 16);
            CP16(dA1 + (uint32_t)(s * ASZ * 4), gA + (size_t)s * 16 + 4);
            CP16(dB0 + (uint32_t)(s * BSZ * 4), gB + (size_t)s * 16);
        }
        CPCOMMIT();
    }

    for (int kt = 0; kt < nk; kt++) {
        CPWAIT2();
        __syncthreads();

        int pk = kt + 3;
        if (pk < nk) {
            int ps = pk & 3;
            CP16(dA0 + (uint32_t)(ps * ASZ * 4), gA + (size_t)pk * 16);
            CP16(dA1 + (uint32_t)(ps * ASZ * 4), gA + (size_t)pk * 16 + 4);
            CP16(dB0 + (uint32_t)(ps * BSZ * 4), gB + (size_t)pk * 16);
        }
        CPCOMMIT();

        const float* As_ = smA + (kt & 3) * ASZ;
        const float* Bs_ = smB + (kt & 3) * BSZ;

        #pragma unroll
        for (int ka = 0; ka < 2; ka++) {
            int k0 = ka * 8;
            uint32_t a[2][4], b[4][2];
            #pragma unroll
            for (int ma = 0; ma < 2; ma++) {
                int base = (wm + ma * 16 + grp) * PADK + k0 + tig;
                a[ma][0] = __float_as_uint(As_[base]);
                a[ma][1] = __float_as_uint(As_[base + 8 * PADK]);
                a[ma][2] = __float_as_uint(As_[base + 4]);
                a[ma][3] = __float_as_uint(As_[base + 8 * PADK + 4]);
            }
            #pragma unroll
            for (int na = 0; na < 4; na++) {
                int base = (wn + na * 8 + grp) * PADK + k0 + tig;
                b[na][0] = __float_as_uint(Bs_[base]);
                b[na][1] = __float_as_uint(Bs_[base + 4]);
            }
            #pragma unroll
            for (int ma = 0; ma < 2; ma++)
                #pragma unroll
                for (int na = 0; na < 4; na++)
                    mma_tf32(c[ma][na], a[ma], b[na]);
        }
        __syncthreads();
    }

    // epilogue
    #pragma unroll
    for (int ma = 0; ma < 2; ma++) {
        int r0 = rowA0 + wm + ma * 16 + grp;
        #pragma unroll
        for (int na = 0; na < 4; na++) {
            int col = colB0 + wn + na * 8 + tig * 2;
            float b0 = bias[col], b1 = bias[col + 1];
            float v0 = c[ma][na][0] + b0, v1 = c[ma][na][1] + b1;
            float v2 = c[ma][na][2] + b0, v3 = c[ma][na][3] + b1;
            if (relu) {
                v0 = fmaxf(v0, 0.0f); v1 = fmaxf(v1, 0.0f);
                v2 = fmaxf(v2, 0.0f); v3 = fmaxf(v3, 0.0f);
            }
            if (rnd) {
                v0 = tf32_rna(v0); v1 = tf32_rna(v1);
                v2 = tf32_rna(v2); v3 = tf32_rna(v3);
            }
            *(float2*)&C[(size_t)r0 * DDIM + col]       = make_float2(v0, v1);
            *(float2*)&C[(size_t)(r0 + 8) * DDIM + col] = make_float2(v2, v3);
        }
    }
}

// ---------------- heads: cls (81) + reg (320), fp32 ----------------
__global__ void __launch_bounds__(256)
heads_kernel(const float* __restrict__ Z,
             const float* __restrict__ Wc, const float* __restrict__ bc,
             const float* __restrict__ Wr, const float* __restrict__ br,
             float* __restrict__ out) {
    __shared__ float zs[8][DDIM];
    int m0 = blockIdx.x * 8;
    for (int i = threadIdx.x; i < 8 * DDIM; i += blockDim.x)
        zs[i >> 10][i & 1023] = Z[(size_t)(m0 + (i >> 10)) * DDIM + (i & 1023)];
    __syncthreads();

    for (int n = threadIdx.x; n < NCLS + NREG; n += blockDim.x) {
        const float* w; float bb;
        if (n < NCLS) { w = Wc + (size_t)n * DDIM; bb = bc[n]; }
        else          { w = Wr + (size_t)(n - NCLS) * DDIM; bb = br[n - NCLS]; }
        float acc[8];
        #pragma unroll
        for (int r = 0; r < 8; r++) acc[r] = bb;
        for (int k = 0; k < DDIM; k += 4) {
            float4 wv = *(const float4*)(w + k);
            #pragma unroll
            for (int r = 0; r < 8; r++) {
                acc[r] = fmaf(zs[r][k + 0], wv.x, acc[r]);
                acc[r] = fmaf(zs[r][k + 1], wv.y, acc[r]);
                acc[r] = fmaf(zs[r][k + 2], wv.z, acc[r]);
                acc[r] = fmaf(zs[r][k + 3], wv.w, acc[r]);
            }
        }
        #pragma unroll
        for (int r = 0; r < 8; r++) {
            int m = m0 + r;
            if (n < NCLS) out[(size_t)m * NCLS + n] = acc[r];
            else out[(size_t)NROI * NCLS + (size_t)m * NREG + (n - NCLS)] = acc[r];
        }
    }
}

// ---------------- launch ----------------
extern "C" void kernel_launch(void* const* d_in, const int* in_sizes, int n_in,
                              void* d_out, int out_size) {
    const float* f2   = (const float*)d_in[0];
    const float* f3   = (const float*)d_in[1];
    const float* f4   = (const float*)d_in[2];
    const float* f5   = (const float*)d_in[3];
    const float* rois = (const float*)d_in[4];
    const float* W1   = (const float*)d_in[5];
    const float* b1   = (const float*)d_in[6];
    const float* W2   = (const float*)d_in[7];
    const float* b2   = (const float*)d_in[8];
    const float* Wc   = (const float*)d_in[9];
    const float* bc   = (const float*)d_in[10];
    const float* Wr   = (const float*)d_in[11];
    const float* br   = (const float*)d_in[12];
    float* out = (float*)d_out;

    float *X, *Y, *Z, *W1r, *W2r;
    cudaGetSymbolAddress((void**)&X, g_X);
    cudaGetSymbolAddress((void**)&Y, g_Y);
    cudaGetSymbolAddress((void**)&Z, g_Z);
    cudaGetSymbolAddress((void**)&W1r, g_W1r);
    cudaGetSymbolAddress((void**)&W2r, g_W2r);

    cudaFuncSetAttribute(gemm_mma_tf32, cudaFuncAttributeMaxDynamicSharedMemorySize, GSMEM);

    roi_prep_kernel<<<(NROI + 255) / 256, 256>>>(rois);

    int total = NROI * CH * NPIX;
    roi_align_kernel<<<(total + 255) / 256, 256>>>(f2, f3, f4, f5);

    int n4w1 = DDIM * FDIM / 4, n4w2 = DDIM * DDIM / 4;
    round_tf32_kernel<<<(n4w1 + 255) / 256, 256>>>((const float4*)W1, (float4*)W1r, n4w1);
    round_tf32_kernel<<<(n4w2 + 255) / 256, 256>>>((const float4*)W2, (float4*)W2r, n4w2);

    // fc1: [1024,12544] x [1024,12544]^T -> [1024,1024], relu, tf32-round output
    gemm_mma_tf32<<<dim3(DDIM / 64, NROI / 128), 256, GSMEM>>>(X, W1r, b1, Y, FDIM, 1, 1);
    // fc2: [1024,1024] x [1024,1024]^T -> [1024,1024], relu
    gemm_mma_tf32<<<dim3(DDIM / 64, NROI / 128), 256, GSMEM>>>(Y, W2r, b2, Z, DDIM, 1, 0);

    heads_kernel<<<NROI / 8, 256>>>(Z, Wc, bc, Wr, br, out);
}

// round 4
// speedup vs baseline: 2.4460x; 1.0172x over previous
#include <cuda_runtime.h>
#include <cstdint>
#include <math.h>

// ---------------- problem constants ----------------
#define NBS   2
#define NR    512
#define NROI  (NBS*NR)          // 1024
#define CH    256
#define OUTS  7
#define NPIX  (OUTS*OUTS)       // 49
#define FDIM  (CH*NPIX)         // 12544
#define DDIM  1024
#define NCLS  81
#define NREG  320

// ---------------- device scratch ----------------
__device__ float g_X[(size_t)NROI * FDIM];     // pooled roi features (tf32-rounded)
__device__ float g_Y[(size_t)NROI * DDIM];     // fc1 out (tf32-rounded)
__device__ float g_Z[(size_t)NROI * DDIM];     // fc2 out (fp32)
__device__ float g_W1r[(size_t)DDIM * FDIM];   // tf32-rounded W1
__device__ float g_W2r[(size_t)DDIM * DDIM];   // tf32-rounded W2
__device__ int   g_lvl[NROI];
__device__ float g_meta[NROI * 4];

// ---------------- helpers ----------------
__device__ __forceinline__ float tf32_rna(float x) {
    uint32_t r; asm("cvt.rna.tf32.f32 %0, %1;" : "=r"(r) : "f"(x));
    return __uint_as_float(r);
}
__device__ __forceinline__ uint32_t smem_u32(const void* p) {
    uint32_t a;
    asm("{ .reg .u64 t; cvta.to.shared.u64 t, %1; cvt.u32.u64 %0, t; }" : "=r"(a) : "l"(p));
    return a;
}
#define CP16(dst, src) \
    asm volatile("cp.async.cg.shared.global [%0], [%1], 16;" :: "r"(dst), "l"(src) : "memory")
#define CPCOMMIT() asm volatile("cp.async.commit_group;" ::: "memory")
#define CPWAIT3()  asm volatile("cp.async.wait_group 3;" ::: "memory")

__device__ __forceinline__ void mma_tf32(float c[4], const uint32_t a[4], const uint32_t b[2]) {
    asm volatile(
        "mma.sync.aligned.m16n8k8.row.col.f32.tf32.tf32.f32 "
        "{%0,%1,%2,%3}, {%4,%5,%6,%7}, {%8,%9}, {%0,%1,%2,%3};"
        : "+f"(c[0]), "+f"(c[1]), "+f"(c[2]), "+f"(c[3])
        : "r"(a[0]), "r"(a[1]), "r"(a[2]), "r"(a[3]), "r"(b[0]), "r"(b[1]));
}

// ---------------- roi prep ----------------
__global__ void roi_prep_kernel(const float* __restrict__ rois) {
    int i = blockIdx.x * blockDim.x + threadIdx.x;
    if (i >= NROI) return;
    float x1 = rois[i * 4 + 0], y1 = rois[i * 4 + 1];
    float x2 = rois[i * 4 + 2], y2 = rois[i * 4 + 3];
    float w = x2 - x1, h = y2 - y1;
    float lv = floorf(4.0f + log2f(sqrtf(w * h) / 224.0f + 1e-6f));
    int li = (int)lv - 2;
    g_lvl[i] = li;
    int lic = li < 0 ? 0 : (li > 3 ? 3 : li);
    float scale = 1.0f / (float)(4 << lic);
    float x1s = x1 * scale, y1s = y1 * scale;
    float rw = fmaxf(x2 * scale - x1s, 1.0f);
    float rh = fmaxf(y2 * scale - y1s, 1.0f);
    g_meta[i * 4 + 0] = x1s;
    g_meta[i * 4 + 1] = y1s;
    g_meta[i * 4 + 2] = rw / (float)OUTS;
    g_meta[i * 4 + 3] = rh / (float)OUTS;
}

// ---------------- roi align: 4 channels per thread ----------------
// thread idx -> (n, c4, p); coords computed once, 4 channel gathers share indices.
__global__ void __launch_bounds__(256)
roi_align_kernel(const float* __restrict__ f2, const float* __restrict__ f3,
                 const float* __restrict__ f4, const float* __restrict__ f5) {
    int idx = blockIdx.x * blockDim.x + threadIdx.x;
    if (idx >= NROI * (CH / 4) * NPIX) return;
    int n   = idx / ((CH / 4) * NPIX);
    int rem = idx - n * ((CH / 4) * NPIX);
    int c4  = rem / NPIX;
    int p   = rem - c4 * NPIX;
    int c0  = c4 * 4;

    size_t obase = (size_t)n * FDIM + (size_t)c0 * NPIX + p;

    int li = g_lvl[n];
    if (li < 0 || li > 3) {
        g_X[obase] = 0.0f; g_X[obase + NPIX] = 0.0f;
        g_X[obase + 2 * NPIX] = 0.0f; g_X[obase + 3 * NPIX] = 0.0f;
        return;
    }

    int ph = p / OUTS, pw = p - ph * OUTS;
    const float* f; int H;
    if      (li == 0) { f = f2; H = 200; }
    else if (li == 1) { f = f3; H = 100; }
    else if (li == 2) { f = f4; H = 50;  }
    else              { f = f5; H = 25;  }
    int W = H;
    int HW = H * W;
    int b = (n >= NR) ? 1 : 0;
    const float* base = f + ((size_t)b * CH + c0) * (size_t)HW;

    float x1 = g_meta[n * 4 + 0], y1 = g_meta[n * 4 + 1];
    float bw = g_meta[n * 4 + 2], bh = g_meta[n * 4 + 3];

    float acc0 = 0.0f, acc1 = 0.0f, acc2 = 0.0f, acc3 = 0.0f;
    #pragma unroll
    for (int iy = 0; iy < 2; iy++) {
        float y = y1 + ((float)ph + 0.25f + 0.5f * (float)iy) * bh;
        bool vy = (y > -1.0f) && (y < (float)H);
        float yc = fminf(fmaxf(y, 0.0f), (float)(H - 1));
        float y0f = floorf(yc);
        int y0 = (int)y0f;
        int yb = min(y0 + 1, H - 1);
        float ly = yc - y0f;
        #pragma unroll
        for (int ix = 0; ix < 2; ix++) {
            float x = x1 + ((float)pw + 0.25f + 0.5f * (float)ix) * bw;
            bool vx = (x > -1.0f) && (x < (float)W);
            if (vy && vx) {
                float xc = fminf(fmaxf(x, 0.0f), (float)(W - 1));
                float x0f = floorf(xc);
                int x0 = (int)x0f;
                int xb = min(x0 + 1, W - 1);
                float lx = xc - x0f;
                float w00 = (1.0f - ly) * (1.0f - lx);
                float w01 = (1.0f - ly) * lx;
                float w10 = ly * (1.0f - lx);
                float w11 = ly * lx;
                int o00 = y0 * W + x0, o01 = y0 * W + xb;
                int o10 = yb * W + x0, o11 = yb * W + xb;
                const float* bc = base;
                acc0 += w00 * bc[o00] + w01 * bc[o01] + w10 * bc[o10] + w11 * bc[o11];
                bc += HW;
                acc1 += w00 * bc[o00] + w01 * bc[o01] + w10 * bc[o10] + w11 * bc[o11];
                bc += HW;
                acc2 += w00 * bc[o00] + w01 * bc[o01] + w10 * bc[o10] + w11 * bc[o11];
                bc += HW;
                acc3 += w00 * bc[o00] + w01 * bc[o01] + w10 * bc[o10] + w11 * bc[o11];
            }
        }
    }
    g_X[obase]            = tf32_rna(acc0 * 0.25f);
    g_X[obase + NPIX]     = tf32_rna(acc1 * 0.25f);
    g_X[obase + 2 * NPIX] = tf32_rna(acc2 * 0.25f);
    g_X[obase + 3 * NPIX] = tf32_rna(acc3 * 0.25f);
}

// ---------------- merged elementwise tf32 round: W1 then W2 ----------------
#define N4W1 (DDIM * FDIM / 4)
#define N4W2 (DDIM * DDIM / 4)
__global__ void round_all_kernel(const float4* __restrict__ w1,
                                 const float4* __restrict__ w2) {
    int i = blockIdx.x * blockDim.x + threadIdx.x;
    const float4* in; float4* out; int j;
    if (i < N4W1) { in = w1; out = (float4*)g_W1r; j = i; }
    else if (i < N4W1 + N4W2) { in = w2; out = (float4*)g_W2r; j = i - N4W1; }
    else return;
    float4 v = in[j];
    v.x = tf32_rna(v.x); v.y = tf32_rna(v.y);
    v.z = tf32_rna(v.z); v.w = tf32_rna(v.w);
    out[j] = v;
}

// ---------------- mma.sync tf32 GEMM ----------------
// C[M,DDIM] = A[M,K] * B[DDIM,K]^T + bias; tile 128x64, BK=16, 5-stage cp.async.
// 256 threads, 8 warps (4 M x 2 N), warp tile 32x32, m16n8k8 atoms.
#define PADK   20
#define ASZ    (128 * PADK)
#define BSZ    (64  * PADK)
#define NSTG   5
#define GSMEM  ((NSTG * (ASZ + BSZ)) * 4)   // 76800 bytes

__global__ void __launch_bounds__(256, 1)
gemm_mma_tf32(const float* __restrict__ A, const float* __restrict__ B,
              const float* __restrict__ bias, float* __restrict__ C,
              int K, int relu, int rnd) {
    extern __shared__ float sm[];
    float* smA = sm;
    float* smB = sm + NSTG * ASZ;
    uint32_t sA = smem_u32(smA);
    uint32_t sB = smem_u32(smB);

    const int tid = threadIdx.x;
    const int wid = tid >> 5, lane = tid & 31;
    const int grp = lane >> 2, tig = lane & 3;
    const int wm = (wid & 3) * 32;
    const int wn = (wid >> 2) * 32;

    const int rowA0 = blockIdx.y * 128;
    const int colB0 = blockIdx.x * 64;
    const int nk = K >> 4;

    const int arow = tid >> 1, ac = (tid & 1) * 8;
    const int brow = tid >> 2, bc = (tid & 3) * 4;
    const float* gA = A + (size_t)(rowA0 + arow) * K + ac;
    const float* gB = B + (size_t)(colB0 + brow) * K + bc;
    const uint32_t dA0 = sA + (uint32_t)(arow * PADK + ac) * 4;
    const uint32_t dA1 = dA0 + 16;
    const uint32_t dB0 = sB + (uint32_t)(brow * PADK + bc) * 4;

    float c[2][4][4];
    #pragma unroll
    for (int i = 0; i < 2; i++)
        #pragma unroll
        for (int j = 0; j < 4; j++)
            #pragma unroll
            for (int q = 0; q < 4; q++) c[i][j][q] = 0.0f;

    // prologue: stages 0..NSTG-2
    #pragma unroll
    for (int s = 0; s < NSTG - 1; s++) {
        if (s < nk) {
            CP16(dA0 + (uint32_t)(s * ASZ * 4), gA + (size_t)s * 16);
            CP16(dA1 + (uint32_t)(s * ASZ * 4), gA + (size_t)s * 16 + 4);
            CP16(dB0 + (uint32_t)(s * BSZ * 4), gB + (size_t)s * 16);
        }
        CPCOMMIT();
    }

    int stage = 0;
    for (int kt = 0; kt < nk; kt++) {
        CPWAIT3();
        __syncthreads();

        int pk = kt + NSTG - 1;
        int ps = stage + (NSTG - 1); if (ps >= NSTG) ps -= NSTG;
        if (pk < nk) {
            CP16(dA0 + (uint32_t)(ps * ASZ * 4), gA + (size_t)pk * 16);
            CP16(dA1 + (uint32_t)(ps * ASZ * 4), gA + (size_t)pk * 16 + 4);
            CP16(dB0 + (uint32_t)(ps * BSZ * 4), gB + (size_t)pk * 16);
        }
        CPCOMMIT();

        const float* As_ = smA + stage * ASZ;
        const float* Bs_ = smB + stage * BSZ;

        #pragma unroll
        for (int ka = 0; ka < 2; ka++) {
            int k0 = ka * 8;
            uint32_t a[2][4], b[4][2];
            #pragma unroll
            for (int ma = 0; ma < 2; ma++) {
                int base = (wm + ma * 16 + grp) * PADK + k0 + tig;
                a[ma][0] = __float_as_uint(As_[base]);
                a[ma][1] = __float_as_uint(As_[base + 8 * PADK]);
                a[ma][2] = __float_as_uint(As_[base + 4]);
                a[ma][3] = __float_as_uint(As_[base + 8 * PADK + 4]);
            }
            #pragma unroll
            for (int na = 0; na < 4; na++) {
                int base = (wn + na * 8 + grp) * PADK + k0 + tig;
                b[na][0] = __float_as_uint(Bs_[base]);
                b[na][1] = __float_as_uint(Bs_[base + 4]);
            }
            #pragma unroll
            for (int ma = 0; ma < 2; ma++)
                #pragma unroll
                for (int na = 0; na < 4; na++)
                    mma_tf32(c[ma][na], a[ma], b[na]);
        }
        // no trailing sync: write stage is NSTG-1 ahead of read stage,
        // and the top-of-loop barrier orders stage reuse across warps.
        if (++stage == NSTG) stage = 0;
    }

    // epilogue
    #pragma unroll
    for (int ma = 0; ma < 2; ma++) {
        int r0 = rowA0 + wm + ma * 16 + grp;
        #pragma unroll
        for (int na = 0; na < 4; na++) {
            int col = colB0 + wn + na * 8 + tig * 2;
            float b0 = bias[col], b1 = bias[col + 1];
            float v0 = c[ma][na][0] + b0, v1 = c[ma][na][1] + b1;
            float v2 = c[ma][na][2] + b0, v3 = c[ma][na][3] + b1;
            if (relu) {
                v0 = fmaxf(v0, 0.0f); v1 = fmaxf(v1, 0.0f);
                v2 = fmaxf(v2, 0.0f); v3 = fmaxf(v3, 0.0f);
            }
            if (rnd) {
                v0 = tf32_rna(v0); v1 = tf32_rna(v1);
                v2 = tf32_rna(v2); v3 = tf32_rna(v3);
            }
            *(float2*)&C[(size_t)r0 * DDIM + col]       = make_float2(v0, v1);
            *(float2*)&C[(size_t)(r0 + 8) * DDIM + col] = make_float2(v2, v3);
        }
    }
}

// ---------------- heads: cls (81) + reg (320), fp32 ----------------
__global__ void __launch_bounds__(256)
heads_kernel(const float* __restrict__ Z,
             const float* __restrict__ Wc, const float* __restrict__ bc,
             const float* __restrict__ Wr, const float* __restrict__ br,
             float* __restrict__ out) {
    __shared__ float zs[8][DDIM];
    int m0 = blockIdx.x * 8;
    for (int i = threadIdx.x; i < 8 * DDIM; i += blockDim.x)
        zs[i >> 10][i & 1023] = Z[(size_t)(m0 + (i >> 10)) * DDIM + (i & 1023)];
    __syncthreads();

    for (int n = threadIdx.x; n < NCLS + NREG; n += blockDim.x) {
        const float* w; float bb;
        if (n < NCLS) { w = Wc + (size_t)n * DDIM; bb = bc[n]; }
        else          { w = Wr + (size_t)(n - NCLS) * DDIM; bb = br[n - NCLS]; }
        float acc[8];
        #pragma unroll
        for (int r = 0; r < 8; r++) acc[r] = bb;
        for (int k = 0; k < DDIM; k += 4) {
            float4 wv = *(const float4*)(w + k);
            #pragma unroll
            for (int r = 0; r < 8; r++) {
                acc[r] = fmaf(zs[r][k + 0], wv.x, acc[r]);
                acc[r] = fmaf(zs[r][k + 1], wv.y, acc[r]);
                acc[r] = fmaf(zs[r][k + 2], wv.z, acc[r]);
                acc[r] = fmaf(zs[r][k + 3], wv.w, acc[r]);
            }
        }
        #pragma unroll
        for (int r = 0; r < 8; r++) {
            int m = m0 + r;
            if (n < NCLS) out[(size_t)m * NCLS + n] = acc[r];
            else out[(size_t)NROI * NCLS + (size_t)m * NREG + (n - NCLS)] = acc[r];
        }
    }
}

// ---------------- launch ----------------
extern "C" void kernel_launch(void* const* d_in, const int* in_sizes, int n_in,
                              void* d_out, int out_size) {
    const float* f2   = (const float*)d_in[0];
    const float* f3   = (const float*)d_in[1];
    const float* f4   = (const float*)d_in[2];
    const float* f5   = (const float*)d_in[3];
    const float* rois = (const float*)d_in[4];
    const float* W1   = (const float*)d_in[5];
    const float* b1   = (const float*)d_in[6];
    const float* W2   = (const float*)d_in[7];
    const float* b2   = (const float*)d_in[8];
    const float* Wc   = (const float*)d_in[9];
    const float* bc   = (const float*)d_in[10];
    const float* Wr   = (const float*)d_in[11];
    const float* br   = (const float*)d_in[12];
    float* out = (float*)d_out;

    float *X, *Y, *Z, *W1r, *W2r;
    cudaGetSymbolAddress((void**)&X, g_X);
    cudaGetSymbolAddress((void**)&Y, g_Y);
    cudaGetSymbolAddress((void**)&Z, g_Z);
    cudaGetSymbolAddress((void**)&W1r, g_W1r);
    cudaGetSymbolAddress((void**)&W2r, g_W2r);

    cudaFuncSetAttribute(gemm_mma_tf32, cudaFuncAttributeMaxDynamicSharedMemorySize, GSMEM);

    // order: prep(0) align(1) round(2) fc1(3) fc2(4) heads(5)
    roi_prep_kernel<<<(NROI + 255) / 256, 256>>>(rois);

    int total = NROI * (CH / 4) * NPIX;
    roi_align_kernel<<<(total + 255) / 256, 256>>>(f2, f3, f4, f5);

    round_all_kernel<<<(N4W1 + N4W2 + 255) / 256, 256>>>((const float4*)W1,
                                                         (const float4*)W2);

    gemm_mma_tf32<<<dim3(DDIM / 64, NROI / 128), 256, GSMEM>>>(X, W1r, b1, Y, FDIM, 1, 1);
    gemm_mma_tf32<<<dim3(DDIM / 64, NROI / 128), 256, GSMEM>>>(Y, W2r, b2, Z, DDIM, 1, 0);

    heads_kernel<<<NROI / 8, 256>>>(Z, Wc, bc, Wr, br, out);
}

// round 5
// speedup vs baseline: 2.5627x; 1.0477x over previous
#include <cuda_runtime.h>
#include <cstdint>
#include <math.h>

// ---------------- problem constants ----------------
#define NBS   2
#define NR    512
#define NROI  (NBS*NR)          // 1024
#define CH    256
#define OUTS  7
#define NPIX  (OUTS*OUTS)       // 49
#define FDIM  (CH*NPIX)         // 12544
#define DDIM  1024
#define NCLS  81
#define NREG  320
#define KS    4                 // split-K factor

// ---------------- device scratch ----------------
__device__ float g_X[(size_t)NROI * FDIM];     // pooled roi features (tf32-rounded)
__device__ float g_Y[(size_t)NROI * DDIM];     // fc1 out (tf32-rounded)
__device__ float g_Z[(size_t)NROI * DDIM];     // fc2 out (fp32)
__device__ float g_W1r[(size_t)DDIM * FDIM];   // tf32-rounded W1
__device__ float g_W2r[(size_t)DDIM * DDIM];   // tf32-rounded W2
__device__ float g_P[(size_t)KS * NROI * DDIM]; // split-K partials (16MB)
__device__ int   g_lvl[NROI];
__device__ float g_meta[NROI * 4];

// ---------------- helpers ----------------
__device__ __forceinline__ float tf32_rna(float x) {
    uint32_t r; asm("cvt.rna.tf32.f32 %0, %1;" : "=r"(r) : "f"(x));
    return __uint_as_float(r);
}
__device__ __forceinline__ uint32_t smem_u32(const void* p) {
    uint32_t a;
    asm("{ .reg .u64 t; cvta.to.shared.u64 t, %1; cvt.u32.u64 %0, t; }" : "=r"(a) : "l"(p));
    return a;
}
#define CP16(dst, src) \
    asm volatile("cp.async.cg.shared.global [%0], [%1], 16;" :: "r"(dst), "l"(src) : "memory")
#define CPCOMMIT() asm volatile("cp.async.commit_group;" ::: "memory")
#define CPWAIT3()  asm volatile("cp.async.wait_group 3;" ::: "memory")

__device__ __forceinline__ void mma_tf32(float c[4], const uint32_t a[4], const uint32_t b[2]) {
    asm volatile(
        "mma.sync.aligned.m16n8k8.row.col.f32.tf32.tf32.f32 "
        "{%0,%1,%2,%3}, {%4,%5,%6,%7}, {%8,%9}, {%0,%1,%2,%3};"
        : "+f"(c[0]), "+f"(c[1]), "+f"(c[2]), "+f"(c[3])
        : "r"(a[0]), "r"(a[1]), "r"(a[2]), "r"(a[3]), "r"(b[0]), "r"(b[1]));
}

// ---------------- roi prep ----------------
__global__ void roi_prep_kernel(const float* __restrict__ rois) {
    int i = blockIdx.x * blockDim.x + threadIdx.x;
    if (i >= NROI) return;
    float x1 = rois[i * 4 + 0], y1 = rois[i * 4 + 1];
    float x2 = rois[i * 4 + 2], y2 = rois[i * 4 + 3];
    float w = x2 - x1, h = y2 - y1;
    float lv = floorf(4.0f + log2f(sqrtf(w * h) / 224.0f + 1e-6f));
    int li = (int)lv - 2;
    g_lvl[i] = li;
    int lic = li < 0 ? 0 : (li > 3 ? 3 : li);
    float scale = 1.0f / (float)(4 << lic);
    float x1s = x1 * scale, y1s = y1 * scale;
    float rw = fmaxf(x2 * scale - x1s, 1.0f);
    float rh = fmaxf(y2 * scale - y1s, 1.0f);
    g_meta[i * 4 + 0] = x1s;
    g_meta[i * 4 + 1] = y1s;
    g_meta[i * 4 + 2] = rw / (float)OUTS;
    g_meta[i * 4 + 3] = rh / (float)OUTS;
}

// ---------------- roi align: 4 channels/thread, branch-free gathers ----------
__global__ void __launch_bounds__(256)
roi_align_kernel(const float* __restrict__ f2, const float* __restrict__ f3,
                 const float* __restrict__ f4, const float* __restrict__ f5) {
    int idx = blockIdx.x * blockDim.x + threadIdx.x;
    if (idx >= NROI * (CH / 4) * NPIX) return;
    int n   = idx / ((CH / 4) * NPIX);
    int rem = idx - n * ((CH / 4) * NPIX);
    int c4  = rem / NPIX;
    int p   = rem - c4 * NPIX;
    int c0  = c4 * 4;

    size_t obase = (size_t)n * FDIM + (size_t)c0 * NPIX + p;

    int li = g_lvl[n];
    if (li < 0 || li > 3) {
        g_X[obase] = 0.0f; g_X[obase + NPIX] = 0.0f;
        g_X[obase + 2 * NPIX] = 0.0f; g_X[obase + 3 * NPIX] = 0.0f;
        return;
    }

    int ph = p / OUTS, pw = p - ph * OUTS;
    const float* f; int H;
    if      (li == 0) { f = f2; H = 200; }
    else if (li == 1) { f = f3; H = 100; }
    else if (li == 2) { f = f4; H = 50;  }
    else              { f = f5; H = 25;  }
    int W = H;
    int HW = H * W;
    int b = (n >= NR) ? 1 : 0;
    const float* base = f + ((size_t)b * CH + c0) * (size_t)HW;

    float x1 = g_meta[n * 4 + 0], y1 = g_meta[n * 4 + 1];
    float bw = g_meta[n * 4 + 2], bh = g_meta[n * 4 + 3];

    // precompute per-axis sample data (always clamped; validity folded to weights)
    int yo0[2], yo1[2]; float lys[2]; float vyf[2];
    int xo0[2], xo1[2]; float lxs[2]; float vxf[2];
    #pragma unroll
    for (int i = 0; i < 2; i++) {
        float y = y1 + ((float)ph + 0.25f + 0.5f * (float)i) * bh;
        vyf[i] = ((y > -1.0f) && (y < (float)H)) ? 1.0f : 0.0f;
        float yc = fminf(fmaxf(y, 0.0f), (float)(H - 1));
        float y0f = floorf(yc);
        int y0 = (int)y0f;
        yo0[i] = y0 * W;
        yo1[i] = min(y0 + 1, H - 1) * W;
        lys[i] = yc - y0f;

        float x = x1 + ((float)pw + 0.25f + 0.5f * (float)i) * bw;
        vxf[i] = ((x > -1.0f) && (x < (float)W)) ? 1.0f : 0.0f;
        float xc = fminf(fmaxf(x, 0.0f), (float)(W - 1));
        float x0f = floorf(xc);
        xo0[i] = (int)x0f;
        xo1[i] = min((int)x0f + 1, W - 1);
        lxs[i] = xc - x0f;
    }

    // 4 samples x 4 neighbors: offsets + masked weights
    int   off[16];
    float wgt[16];
    #pragma unroll
    for (int iy = 0; iy < 2; iy++) {
        #pragma unroll
        for (int ix = 0; ix < 2; ix++) {
            float v = vyf[iy] * vxf[ix];
            float ly = lys[iy], lx = lxs[ix];
            int s = (iy * 2 + ix) * 4;
            off[s + 0] = yo0[iy] + xo0[ix]; wgt[s + 0] = v * (1.0f - ly) * (1.0f - lx);
            off[s + 1] = yo0[iy] + xo1[ix]; wgt[s + 1] = v * (1.0f - ly) * lx;
            off[s + 2] = yo1[iy] + xo0[ix]; wgt[s + 2] = v * ly * (1.0f - lx);
            off[s + 3] = yo1[iy] + xo1[ix]; wgt[s + 3] = v * ly * lx;
        }
    }

    #pragma unroll
    for (int c = 0; c < 4; c++) {
        const float* bc = base + (size_t)c * HW;
        float v[16];
        #pragma unroll
        for (int q = 0; q < 16; q++) v[q] = bc[off[q]];   // unconditional, batched
        float acc = 0.0f;
        #pragma unroll
        for (int q = 0; q < 16; q++) acc = fmaf(wgt[q], v[q], acc);
        g_X[obase + (size_t)c * NPIX] = tf32_rna(acc * 0.25f);
    }
}

// ---------------- merged elementwise tf32 round: W1 then W2 ----------------
#define N4W1 (DDIM * FDIM / 4)
#define N4W2 (DDIM * DDIM / 4)
__global__ void round_all_kernel(const float4* __restrict__ w1,
                                 const float4* __restrict__ w2) {
    int i = blockIdx.x * blockDim.x + threadIdx.x;
    const float4* in; float4* out; int j;
    if (i < N4W1) { in = w1; out = (float4*)g_W1r; j = i; }
    else if (i < N4W1 + N4W2) { in = w2; out = (float4*)g_W2r; j = i - N4W1; }
    else return;
    float4 v = in[j];
    v.x = tf32_rna(v.x); v.y = tf32_rna(v.y);
    v.z = tf32_rna(v.z); v.w = tf32_rna(v.w);
    out[j] = v;
}

// ---------------- mma.sync tf32 GEMM, split-K partials ----------------
// P[z][M,DDIM] = A[M, Kz] * B[DDIM, Kz]^T ; tile 128x64, BK=16, 5-stage cp.async.
// grid (N/64, M/128, KS), 256 threads, 8 warps (4M x 2N), warp tile 32x32.
#define PADK   20
#define ASZ    (128 * PADK)
#define BSZ    (64  * PADK)
#define NSTG   5
#define GSMEM  ((NSTG * (ASZ + BSZ)) * 4)   // 76800 bytes

__global__ void __launch_bounds__(256, 2)
gemm_mma_tf32(const float* __restrict__ A, const float* __restrict__ B,
              float* __restrict__ P, int K, int kc /* iters per split */) {
    extern __shared__ float sm[];
    float* smA = sm;
    float* smB = sm + NSTG * ASZ;
    uint32_t sA = smem_u32(smA);
    uint32_t sB = smem_u32(smB);

    const int tid = threadIdx.x;
    const int wid = tid >> 5, lane = tid & 31;
    const int grp = lane >> 2, tig = lane & 3;
    const int wm = (wid & 3) * 32;
    const int wn = (wid >> 2) * 32;

    const int rowA0 = blockIdx.y * 128;
    const int colB0 = blockIdx.x * 64;
    const int part  = blockIdx.z;
    const int kbase = part * kc * 16;           // element offset in K
    const int nk = kc;

    const int arow = tid >> 1, ac = (tid & 1) * 8;
    const int brow = tid >> 2, bc = (tid & 3) * 4;
    const float* gA = A + (size_t)(rowA0 + arow) * K + kbase + ac;
    const float* gB = B + (size_t)(colB0 + brow) * K + kbase + bc;
    const uint32_t dA0 = sA + (uint32_t)(arow * PADK + ac) * 4;
    const uint32_t dA1 = dA0 + 16;
    const uint32_t dB0 = sB + (uint32_t)(brow * PADK + bc) * 4;

    float c[2][4][4];
    #pragma unroll
    for (int i = 0; i < 2; i++)
        #pragma unroll
        for (int j = 0; j < 4; j++)
            #pragma unroll
            for (int q = 0; q < 4; q++) c[i][j][q] = 0.0f;

    #pragma unroll
    for (int s = 0; s < NSTG - 1; s++) {
        if (s < nk) {
            CP16(dA0 + (uint32_t)(s * ASZ * 4), gA + (size_t)s * 16);
            CP16(dA1 + (uint32_t)(s * ASZ * 4), gA + (size_t)s * 16 + 4);
            CP16(dB0 + (uint32_t)(s * BSZ * 4), gB + (size_t)s * 16);
        }
        CPCOMMIT();
    }

    int stage = 0;
    for (int kt = 0; kt < nk; kt++) {
        CPWAIT3();
        __syncthreads();

        int pk = kt + NSTG - 1;
        int ps = stage + (NSTG - 1); if (ps >= NSTG) ps -= NSTG;
        if (pk < nk) {
            CP16(dA0 + (uint32_t)(ps * ASZ * 4), gA + (size_t)pk * 16);
            CP16(dA1 + (uint32_t)(ps * ASZ * 4), gA + (size_t)pk * 16 + 4);
            CP16(dB0 + (uint32_t)(ps * BSZ * 4), gB + (size_t)pk * 16);
        }
        CPCOMMIT();

        const float* As_ = smA + stage * ASZ;
        const float* Bs_ = smB + stage * BSZ;

        #pragma unroll
        for (int ka = 0; ka < 2; ka++) {
            int k0 = ka * 8;
            uint32_t a[2][4], b[4][2];
            #pragma unroll
            for (int ma = 0; ma < 2; ma++) {
                int base = (wm + ma * 16 + grp) * PADK + k0 + tig;
                a[ma][0] = __float_as_uint(As_[base]);
                a[ma][1] = __float_as_uint(As_[base + 8 * PADK]);
                a[ma][2] = __float_as_uint(As_[base + 4]);
                a[ma][3] = __float_as_uint(As_[base + 8 * PADK + 4]);
            }
            #pragma unroll
            for (int na = 0; na < 4; na++) {
                int base = (wn + na * 8 + grp) * PADK + k0 + tig;
                b[na][0] = __float_as_uint(Bs_[base]);
                b[na][1] = __float_as_uint(Bs_[base + 4]);
            }
            #pragma unroll
            for (int ma = 0; ma < 2; ma++)
                #pragma unroll
                for (int na = 0; na < 4; na++)
                    mma_tf32(c[ma][na], a[ma], b[na]);
        }
        if (++stage == NSTG) stage = 0;
    }

    // epilogue: raw partial sums
    float* Pp = P + (size_t)part * NROI * DDIM;
    #pragma unroll
    for (int ma = 0; ma < 2; ma++) {
        int r0 = rowA0 + wm + ma * 16 + grp;
        #pragma unroll
        for (int na = 0; na < 4; na++) {
            int col = colB0 + wn + na * 8 + tig * 2;
            *(float2*)&Pp[(size_t)r0 * DDIM + col]       = make_float2(c[ma][na][0], c[ma][na][1]);
            *(float2*)&Pp[(size_t)(r0 + 8) * DDIM + col] = make_float2(c[ma][na][2], c[ma][na][3]);
        }
    }
}

// ---------------- split-K reduce + bias + relu (+ tf32 round) ----------------
__global__ void __launch_bounds__(256)
reduce_kernel(const float* __restrict__ bias, float* __restrict__ C, int rnd) {
    int i = blockIdx.x * blockDim.x + threadIdx.x;   // float4 index over [1024x1024]
    if (i >= NROI * DDIM / 4) return;
    const float4* P = (const float4*)g_P;
    const size_t stride = (size_t)NROI * DDIM / 4;
    float4 v0 = P[i];
    float4 v1 = P[i + stride];
    float4 v2 = P[i + 2 * stride];
    float4 v3 = P[i + 3 * stride];
    int col = (i * 4) & (DDIM - 1);
    float4 bv = *(const float4*)&bias[col];
    float4 r;
    r.x = fmaxf((v0.x + v1.x) + (v2.x + v3.x) + bv.x, 0.0f);
    r.y = fmaxf((v0.y + v1.y) + (v2.y + v3.y) + bv.y, 0.0f);
    r.z = fmaxf((v0.z + v1.z) + (v2.z + v3.z) + bv.z, 0.0f);
    r.w = fmaxf((v0.w + v1.w) + (v2.w + v3.w) + bv.w, 0.0f);
    if (rnd) { r.x = tf32_rna(r.x); r.y = tf32_rna(r.y);
               r.z = tf32_rna(r.z); r.w = tf32_rna(r.w); }
    ((float4*)C)[i] = r;
}

// ---------------- heads: cls (81) + reg (320), fp32 ----------------
__global__ void __launch_bounds__(256)
heads_kernel(const float* __restrict__ Z,
             const float* __restrict__ Wc, const float* __restrict__ bc,
             const float* __restrict__ Wr, const float* __restrict__ br,
             float* __restrict__ out) {
    __shared__ float zs[8][DDIM];
    int m0 = blockIdx.x * 8;
    for (int i = threadIdx.x; i < 8 * DDIM; i += blockDim.x)
        zs[i >> 10][i & 1023] = Z[(size_t)(m0 + (i >> 10)) * DDIM + (i & 1023)];
    __syncthreads();

    for (int n = threadIdx.x; n < NCLS + NREG; n += blockDim.x) {
        const float* w; float bb;
        if (n < NCLS) { w = Wc + (size_t)n * DDIM; bb = bc[n]; }
        else          { w = Wr + (size_t)(n - NCLS) * DDIM; bb = br[n - NCLS]; }
        float acc[8];
        #pragma unroll
        for (int r = 0; r < 8; r++) acc[r] = bb;
        for (int k = 0; k < DDIM; k += 4) {
            float4 wv = *(const float4*)(w + k);
            #pragma unroll
            for (int r = 0; r < 8; r++) {
                acc[r] = fmaf(zs[r][k + 0], wv.x, acc[r]);
                acc[r] = fmaf(zs[r][k + 1], wv.y, acc[r]);
                acc[r] = fmaf(zs[r][k + 2], wv.z, acc[r]);
                acc[r] = fmaf(zs[r][k + 3], wv.w, acc[r]);
            }
        }
        #pragma unroll
        for (int r = 0; r < 8; r++) {
            int m = m0 + r;
            if (n < NCLS) out[(size_t)m * NCLS + n] = acc[r];
            else out[(size_t)NROI * NCLS + (size_t)m * NREG + (n - NCLS)] = acc[r];
        }
    }
}

// ---------------- launch ----------------
extern "C" void kernel_launch(void* const* d_in, const int* in_sizes, int n_in,
                              void* d_out, int out_size) {
    const float* f2   = (const float*)d_in[0];
    const float* f3   = (const float*)d_in[1];
    const float* f4   = (const float*)d_in[2];
    const float* f5   = (const float*)d_in[3];
    const float* rois = (const float*)d_in[4];
    const float* W1   = (const float*)d_in[5];
    const float* b1   = (const float*)d_in[6];
    const float* W2   = (const float*)d_in[7];
    const float* b2   = (const float*)d_in[8];
    const float* Wc   = (const float*)d_in[9];
    const float* bc   = (const float*)d_in[10];
    const float* Wr   = (const float*)d_in[11];
    const float* br   = (const float*)d_in[12];
    float* out = (float*)d_out;

    float *X, *Y, *Z, *W1r, *W2r, *Pb;
    cudaGetSymbolAddress((void**)&X, g_X);
    cudaGetSymbolAddress((void**)&Y, g_Y);
    cudaGetSymbolAddress((void**)&Z, g_Z);
    cudaGetSymbolAddress((void**)&W1r, g_W1r);
    cudaGetSymbolAddress((void**)&W2r, g_W2r);
    cudaGetSymbolAddress((void**)&Pb, g_P);

    cudaFuncSetAttribute(gemm_mma_tf32, cudaFuncAttributeMaxDynamicSharedMemorySize, GSMEM);

    roi_prep_kernel<<<(NROI + 255) / 256, 256>>>(rois);

    int total = NROI * (CH / 4) * NPIX;
    roi_align_kernel<<<(total + 255) / 256, 256>>>(f2, f3, f4, f5);

    round_all_kernel<<<(N4W1 + N4W2 + 255) / 256, 256>>>((const float4*)W1,
                                                         (const float4*)W2);

    int nred = NROI * DDIM / 4;
    // fc1: K=12544, 784 BK-iters, 196 per split
    gemm_mma_tf32<<<dim3(DDIM / 64, NROI / 128, KS), 256, GSMEM>>>(X, W1r, Pb, FDIM, 196);
    reduce_kernel<<<(nred + 255) / 256, 256>>>(b1, Y, 1);
    // fc2: K=1024, 64 BK-iters, 16 per split
    gemm_mma_tf32<<<dim3(DDIM / 64, NROI / 128, KS), 256, GSMEM>>>(Y, W2r, Pb, DDIM, 16);
    reduce_kernel<<<(nred + 255) / 256, 256>>>(b2, Z, 0);

    heads_kernel<<<NROI / 8, 256>>>(Z, Wc, bc, Wr, br, out);
}